// round 9
// baseline (speedup 1.0000x reference)
#include <cuda_runtime.h>
#include <cuda_fp16.h>
#include <cstdint>

// Shapes (fixed)
#define N_NODES 8192
#define D_IN    200
#define D_OUT   128
#define NEG_SLOPE 0.01f

// K3 tiling (R4-proven: BM=64, 128 GEMM CTAs, 256 thr) + 64 copy CTAs
#define BM        64
#define BKC       64              // K per pipeline chunk (64 fp16 = 128B rows)
#define NCHUNKS   (N_NODES / BKC) // 128
#define STAGES    4
#define A_TILE_B  (BM * BKC * 2)        // 8 KB
#define B_TILE_B  (D_OUT * BKC * 2)     // 16 KB
#define STAGE_B   (A_TILE_B + B_TILE_B) // 24 KB
#define GEMM_CTAS (N_NODES / BM)        // 128
#define COPY_CTAS 64
#define SWZ(off) ((off) ^ (((off) >> 3) & 0x70))

// Scratch (__device__ globals: allocation-free rule)
__device__ float  g_dis[N_NODES];                       // d^{-1/2}
__device__ __half g_Ah[(size_t)N_NODES * N_NODES];      // fp16 sigmoid-clamp(A)
__device__ __half g_Bt[(size_t)D_OUT * N_NODES];        // [n][k] fp16 dis[k]*(HW+b)

// ---------------------------------------------------------------------------
// Kernel 1: sigmoid+clamp -> fp16 g_Ah ONLY (384 MB); rowsum -> rsqrt.
// (measured 57.2us at 80% DRAM). The fp32 A' output is produced by the copy
// CTAs of K3, overlapped with the GEMM.
// ---------------------------------------------------------------------------
__global__ void __launch_bounds__(256) k_sigmoid_rowsum(
    const float* __restrict__ A)
{
    const int row = blockIdx.x;
    const float4* ap = reinterpret_cast<const float4*>(A + (size_t)row * N_NODES);
    uint2* hp = reinterpret_cast<uint2*>(g_Ah + (size_t)row * N_NODES);

    float sum = 0.0f;
    #pragma unroll 2
    for (int i = threadIdx.x; i < N_NODES / 4; i += 256) {
        float4 v = ap[i];
        float4 s;
        s.x = fmaxf(__fdividef(1.0f, 1.0f + __expf(-v.x)), 0.1f);
        s.y = fmaxf(__fdividef(1.0f, 1.0f + __expf(-v.y)), 0.1f);
        s.z = fmaxf(__fdividef(1.0f, 1.0f + __expf(-v.z)), 0.1f);
        s.w = fmaxf(__fdividef(1.0f, 1.0f + __expf(-v.w)), 0.1f);
        __half2 p0 = __floats2half2_rn(s.x, s.y);
        __half2 p1 = __floats2half2_rn(s.z, s.w);
        uint2 u;
        u.x = *reinterpret_cast<uint32_t*>(&p0);
        u.y = *reinterpret_cast<uint32_t*>(&p1);
        hp[i] = u;
        sum += (s.x + s.y) + (s.z + s.w);
    }

    #pragma unroll
    for (int off = 16; off > 0; off >>= 1)
        sum += __shfl_xor_sync(0xFFFFFFFFu, sum, off);

    __shared__ float ws[8];
    const int wid = threadIdx.x >> 5;
    const int lane = threadIdx.x & 31;
    if (lane == 0) ws[wid] = sum;
    __syncthreads();
    if (threadIdx.x == 0) {
        float tot = 0.0f;
        #pragma unroll
        for (int w = 0; w < 8; w++) tot += ws[w];
        g_dis[row] = rsqrtf(tot);
    }
}

// ---------------------------------------------------------------------------
// Kernel 2: g_Bt[j][k] = fp16( dis[k] * (H[k,:]@W[:,j] + b[j]) ) (transposed)
// ---------------------------------------------------------------------------
#define K2_ROWS 16
__global__ void __launch_bounds__(256) k_hw(
    const float* __restrict__ H, const float* __restrict__ W,
    const float* __restrict__ b)
{
    __shared__ float hs[K2_ROWS][D_IN];
    const int kb = blockIdx.x * K2_ROWS;
    const int tid = threadIdx.x;

    for (int idx = tid; idx < K2_ROWS * (D_IN / 4); idx += 256) {
        const int r = idx / (D_IN / 4), c = idx % (D_IN / 4);
        reinterpret_cast<float4*>(&hs[r][0])[c] =
            reinterpret_cast<const float4*>(H + (size_t)(kb + r) * D_IN)[c];
    }
    __syncthreads();

    const int ty = tid >> 5;
    const int tx = tid & 31;
    const int j0 = tx * 4;
    const int k0 = kb + ty * 2;

    const float4 bj = *reinterpret_cast<const float4*>(b + j0);
    float4 acc0 = bj, acc1 = bj;
    const float* h0p = hs[ty * 2];
    const float* h1p = hs[ty * 2 + 1];

    #pragma unroll 4
    for (int i = 0; i < D_IN; i++) {
        const float4 w4 = *reinterpret_cast<const float4*>(W + i * D_OUT + j0);
        const float h0 = h0p[i];
        const float h1 = h1p[i];
        acc0.x = fmaf(h0, w4.x, acc0.x);
        acc0.y = fmaf(h0, w4.y, acc0.y);
        acc0.z = fmaf(h0, w4.z, acc0.z);
        acc0.w = fmaf(h0, w4.w, acc0.w);
        acc1.x = fmaf(h1, w4.x, acc1.x);
        acc1.y = fmaf(h1, w4.y, acc1.y);
        acc1.z = fmaf(h1, w4.z, acc1.z);
        acc1.w = fmaf(h1, w4.w, acc1.w);
    }

    const float d0 = g_dis[k0];
    const float d1 = g_dis[k0 + 1];
    __half2 p;
    p = __floats2half2_rn(acc0.x * d0, acc1.x * d1);
    *reinterpret_cast<__half2*>(&g_Bt[(size_t)(j0 + 0) * N_NODES + k0]) = p;
    p = __floats2half2_rn(acc0.y * d0, acc1.y * d1);
    *reinterpret_cast<__half2*>(&g_Bt[(size_t)(j0 + 1) * N_NODES + k0]) = p;
    p = __floats2half2_rn(acc0.z * d0, acc1.z * d1);
    *reinterpret_cast<__half2*>(&g_Bt[(size_t)(j0 + 2) * N_NODES + k0]) = p;
    p = __floats2half2_rn(acc0.w * d0, acc1.w * d1);
    *reinterpret_cast<__half2*>(&g_Bt[(size_t)(j0 + 3) * N_NODES + k0]) = p;
}

// ---------------------------------------------------------------------------
// K3: role-specialized single launch.
//   blocks [0, 128): R4-proven fp16 HMMA GEMM (BM=64, cp.async 4-stage).
//   blocks [128, 192): streaming upconvert g_Ah -> fp32 A' output, overlapped
//   with the GEMM (runs on idle SMs / co-resident, no smem, low regs).
// ---------------------------------------------------------------------------
__device__ __forceinline__ uint32_t s2u(const void* p) {
    uint32_t a;
    asm("{ .reg .u64 t; cvta.to.shared.u64 t, %1; cvt.u32.u64 %0, t; }"
        : "=r"(a) : "l"(p));
    return a;
}
__device__ __forceinline__ void cp16(uint32_t dst, const void* src) {
    asm volatile("cp.async.cg.shared.global [%0], [%1], 16;"
                 :: "r"(dst), "l"(src) : "memory");
}
__device__ __forceinline__ void ldsm4(uint32_t* r, uint32_t addr) {
    asm volatile("ldmatrix.sync.aligned.m8n8.x4.shared.b16 {%0,%1,%2,%3}, [%4];"
                 : "=r"(r[0]), "=r"(r[1]), "=r"(r[2]), "=r"(r[3]) : "r"(addr));
}
__device__ __forceinline__ void hmma(float* d, const uint32_t* a,
                                     uint32_t b0, uint32_t b1) {
    asm volatile(
        "mma.sync.aligned.m16n8k16.row.col.f32.f16.f16.f32 "
        "{%0,%1,%2,%3},{%4,%5,%6,%7},{%8,%9},{%0,%1,%2,%3};"
        : "+f"(d[0]), "+f"(d[1]), "+f"(d[2]), "+f"(d[3])
        : "r"(a[0]), "r"(a[1]), "r"(a[2]), "r"(a[3]), "r"(b0), "r"(b1));
}

__global__ void __launch_bounds__(256, 1) k_gemm_h(
    float* __restrict__ Aout, float* __restrict__ out)
{
    // ================= copy role: blocks [GEMM_CTAS, GEMM_CTAS+COPY_CTAS) ===
    if (blockIdx.x >= GEMM_CTAS) {
        const int cb = blockIdx.x - GEMM_CTAS;
        // each copy CTA owns a contiguous slab of 128 rows = 1M halves
        const size_t base = (size_t)cb * (N_NODES / COPY_CTAS) * N_NODES;
        const uint4* src = reinterpret_cast<const uint4*>(g_Ah + base);  // 8 halves
        float4* dst = reinterpret_cast<float4*>(Aout + base);
        const int units = (N_NODES / COPY_CTAS) * N_NODES / 8;           // 131072
        for (int i = threadIdx.x; i < units; i += 256) {
            const uint4 u = src[i];
            const __half2* h = reinterpret_cast<const __half2*>(&u);
            const float2 f0 = __half22float2(h[0]);
            const float2 f1 = __half22float2(h[1]);
            const float2 f2 = __half22float2(h[2]);
            const float2 f3 = __half22float2(h[3]);
            dst[i * 2]     = make_float4(f0.x, f0.y, f1.x, f1.y);
            dst[i * 2 + 1] = make_float4(f2.x, f2.y, f3.x, f3.y);
        }
        return;
    }

    // ================= GEMM role: blocks [0, GEMM_CTAS) — R4-proven =========
    extern __shared__ __align__(1024) char dsm[];   // STAGES * 24KB = 96KB
    const int t   = threadIdx.x;
    const int wid = t >> 5, lane = t & 31;
    const int wm  = wid & 1;          // m slab (0..1) * 32
    const int wn  = wid >> 1;         // n slab (0..3) * 32
    const int m0  = blockIdx.x * BM;
    const uint32_t smBase = s2u(dsm);

    // ---- staging maps: 16B chunks, 128B rows, XOR swizzle
    const int sr  = t >> 3;           // 0..31
    const int sc  = (t & 7) * 16;     // byte col in 128B row
    const __half* srcA = g_Ah + (size_t)(m0 + sr) * N_NODES + (t & 7) * 8;
    const __half* srcB = g_Bt + (size_t)sr * N_NODES + (t & 7) * 8;
    const uint32_t dstA = SWZ(sr * 128 + sc);           // + 4096 for rows+32
    const uint32_t dstB = SWZ(sr * 128 + sc);           // + 4096 per 32 rows

    // ---- ldmatrix address components
    const int lr16 = lane & 15;
    const int lhalf = (lane >> 4) * 16;
    uint32_t aBase[2], bBase[2];
    #pragma unroll
    for (int mt = 0; mt < 2; mt++)
        aBase[mt] = (wm * 32 + mt * 16 + lr16) * 128 + lhalf;
    #pragma unroll
    for (int bt = 0; bt < 2; bt++)
        bBase[bt] = (wn * 32 + bt * 16 + lr16) * 128 + lhalf;

    float acc[2][4][4];
    #pragma unroll
    for (int mt = 0; mt < 2; mt++)
        #pragma unroll
        for (int nt = 0; nt < 4; nt++)
            #pragma unroll
            for (int r = 0; r < 4; r++) acc[mt][nt][r] = 0.0f;

    // ---- prologue: issue STAGES-1 chunks
    #pragma unroll
    for (int c = 0; c < STAGES - 1; c++) {
        const uint32_t sA = smBase + c * STAGE_B;
        const uint32_t sB = sA + A_TILE_B;
        const int ko = c * BKC;
        cp16(sA + dstA,        srcA + ko);
        cp16(sA + dstA + 4096, srcA + ko + 32ull * N_NODES);
        #pragma unroll
        for (int rb = 0; rb < 4; rb++)
            cp16(sB + dstB + rb * 4096, srcB + ko + (size_t)rb * 32 * N_NODES);
        asm volatile("cp.async.commit_group;" ::: "memory");
    }

    for (int c = 0; c < NCHUNKS; c++) {
        asm volatile("cp.async.wait_group %0;" :: "n"(STAGES - 2) : "memory");
        __syncthreads();

        const uint32_t sA = smBase + (c & (STAGES - 1)) * STAGE_B;
        const uint32_t sB = sA + A_TILE_B;

        #pragma unroll
        for (int kk = 0; kk < BKC / 16; kk++) {
            uint32_t aF[2][4], bF[2][4];
            #pragma unroll
            for (int mt = 0; mt < 2; mt++)
                ldsm4(aF[mt], sA + SWZ(aBase[mt] + kk * 32));
            #pragma unroll
            for (int bt = 0; bt < 2; bt++)
                ldsm4(bF[bt], sB + SWZ(bBase[bt] + kk * 32));
            #pragma unroll
            for (int mt = 0; mt < 2; mt++)
                #pragma unroll
                for (int nt = 0; nt < 4; nt++)
                    hmma(acc[mt][nt], aF[mt],
                         bF[nt >> 1][nt & 1], bF[nt >> 1][(nt & 1) + 2]);
        }

        // issue chunk c + STAGES-1
        const int cn = c + STAGES - 1;
        if (cn < NCHUNKS) {
            const uint32_t nA = smBase + (cn & (STAGES - 1)) * STAGE_B;
            const uint32_t nB = nA + A_TILE_B;
            const int ko = cn * BKC;
            cp16(nA + dstA,        srcA + ko);
            cp16(nA + dstA + 4096, srcA + ko + 32ull * N_NODES);
            #pragma unroll
            for (int rb = 0; rb < 4; rb++)
                cp16(nB + dstB + rb * 4096, srcB + ko + (size_t)rb * 32 * N_NODES);
        }
        asm volatile("cp.async.commit_group;" ::: "memory");
    }

    // ---- epilogue: scale by dis[i], LeakyReLU, store
    const int gid = lane >> 2;
    const int cid = (lane & 3) * 2;
    #pragma unroll
    for (int mt = 0; mt < 2; mt++) {
        const int r0 = m0 + wm * 32 + mt * 16 + gid;
        const float d0 = g_dis[r0];
        const float d1 = g_dis[r0 + 8];
        #pragma unroll
        for (int nt = 0; nt < 4; nt++) {
            const int col = wn * 32 + nt * 8 + cid;
            float v0 = d0 * acc[mt][nt][0];
            float v1 = d0 * acc[mt][nt][1];
            float v2 = d1 * acc[mt][nt][2];
            float v3 = d1 * acc[mt][nt][3];
            v0 = (v0 >= 0.0f) ? v0 : NEG_SLOPE * v0;
            v1 = (v1 >= 0.0f) ? v1 : NEG_SLOPE * v1;
            v2 = (v2 >= 0.0f) ? v2 : NEG_SLOPE * v2;
            v3 = (v3 >= 0.0f) ? v3 : NEG_SLOPE * v3;
            *reinterpret_cast<float2*>(out + (size_t)r0 * D_OUT + col)
                = make_float2(v0, v1);
            *reinterpret_cast<float2*>(out + (size_t)(r0 + 8) * D_OUT + col)
                = make_float2(v2, v3);
        }
    }
}

// ---------------------------------------------------------------------------
extern "C" void kernel_launch(void* const* d_in, const int* in_sizes, int n_in,
                              void* d_out, int out_size)
{
    const float* H = (const float*)d_in[0];   // [8192, 200]
    const float* A = (const float*)d_in[1];   // [8192, 8192]
    const float* W = (const float*)d_in[2];   // [200, 128]
    const float* b = (const float*)d_in[3];   // [128]

    float* out  = (float*)d_out;                     // [8192, 128]
    float* Aout = out + (size_t)N_NODES * D_OUT;     // [8192, 8192] A' (fp32)

    k_sigmoid_rowsum<<<N_NODES, 256>>>(A);
    k_hw<<<N_NODES / K2_ROWS, 256>>>(H, W, b);

    cudaFuncSetAttribute(k_gemm_h, cudaFuncAttributeMaxDynamicSharedMemorySize,
                         STAGES * STAGE_B);
    k_gemm_h<<<GEMM_CTAS + COPY_CTAS, 256, STAGES * STAGE_B>>>(Aout, out);
}

// round 10
// speedup vs baseline: 1.6720x; 1.6720x over previous
#include <cuda_runtime.h>
#include <cuda_fp16.h>
#include <cstdint>

// Shapes (fixed)
#define N_NODES 8192
#define D_IN    200
#define D_OUT   128
#define NEG_SLOPE 0.01f

// K3 tiling (R4 mainloop; A staged as fp32 + in-smem convert)
#define BM      64
#define BKC     64                     // K per chunk
#define NCHUNKS (N_NODES / BKC)        // 128
#define STAGES  4
#define A32_TILE_B (BM * BKC * 4)      // 16 KB fp32 A staging
#define B_TILE_B   (D_OUT * BKC * 2)   // 16 KB fp16 B
#define STAGE_B    (A32_TILE_B + B_TILE_B)        // 32 KB
#define A16_OFF    (STAGES * STAGE_B)             // 128 KB
#define A16_BUF_B  (BM * BKC * 2)                 // 8 KB
#define SMEM_TOT   (A16_OFF + 2 * A16_BUF_B)      // 144 KB
#define SWZ(off) ((off) ^ (((off) >> 3) & 0x70))

// Scratch (__device__ globals: allocation-free rule)
__device__ float  g_dis[N_NODES];                // d^{-1/2}
__device__ __half g_Bt[(size_t)D_OUT * N_NODES]; // [n][k] fp16 dis[k]*(HW+b)

// ---------------------------------------------------------------------------
// Kernel 1: A' = max(sigmoid(A), 0.1) -> fp32 output ONLY (512 MB); rowsums.
// ---------------------------------------------------------------------------
__global__ void __launch_bounds__(256) k_sigmoid_rowsum(
    const float* __restrict__ A, float* __restrict__ Aout)
{
    const int row = blockIdx.x;
    const float4* ap = reinterpret_cast<const float4*>(A + (size_t)row * N_NODES);
    float4* op = reinterpret_cast<float4*>(Aout + (size_t)row * N_NODES);

    float sum = 0.0f;
    #pragma unroll 2
    for (int i = threadIdx.x; i < N_NODES / 4; i += 256) {
        float4 v = ap[i];
        float4 s;
        s.x = fmaxf(__fdividef(1.0f, 1.0f + __expf(-v.x)), 0.1f);
        s.y = fmaxf(__fdividef(1.0f, 1.0f + __expf(-v.y)), 0.1f);
        s.z = fmaxf(__fdividef(1.0f, 1.0f + __expf(-v.z)), 0.1f);
        s.w = fmaxf(__fdividef(1.0f, 1.0f + __expf(-v.w)), 0.1f);
        op[i] = s;
        sum += (s.x + s.y) + (s.z + s.w);
    }

    #pragma unroll
    for (int off = 16; off > 0; off >>= 1)
        sum += __shfl_xor_sync(0xFFFFFFFFu, sum, off);

    __shared__ float ws[8];
    const int wid = threadIdx.x >> 5;
    const int lane = threadIdx.x & 31;
    if (lane == 0) ws[wid] = sum;
    __syncthreads();
    if (threadIdx.x == 0) {
        float tot = 0.0f;
        #pragma unroll
        for (int w = 0; w < 8; w++) tot += ws[w];
        g_dis[row] = rsqrtf(tot);
    }
}

// ---------------------------------------------------------------------------
// Kernel 2: g_Bt[j][k] = fp16( dis[k] * (H[k,:]@W[:,j] + b[j]) ) (transposed)
// ---------------------------------------------------------------------------
#define K2_ROWS 16
__global__ void __launch_bounds__(256) k_hw(
    const float* __restrict__ H, const float* __restrict__ W,
    const float* __restrict__ b)
{
    __shared__ float hs[K2_ROWS][D_IN];
    const int kb = blockIdx.x * K2_ROWS;
    const int tid = threadIdx.x;

    for (int idx = tid; idx < K2_ROWS * (D_IN / 4); idx += 256) {
        const int r = idx / (D_IN / 4), c = idx % (D_IN / 4);
        reinterpret_cast<float4*>(&hs[r][0])[c] =
            reinterpret_cast<const float4*>(H + (size_t)(kb + r) * D_IN)[c];
    }
    __syncthreads();

    const int ty = tid >> 5;
    const int tx = tid & 31;
    const int j0 = tx * 4;
    const int k0 = kb + ty * 2;

    const float4 bj = *reinterpret_cast<const float4*>(b + j0);
    float4 acc0 = bj, acc1 = bj;
    const float* h0p = hs[ty * 2];
    const float* h1p = hs[ty * 2 + 1];

    #pragma unroll 4
    for (int i = 0; i < D_IN; i++) {
        const float4 w4 = *reinterpret_cast<const float4*>(W + i * D_OUT + j0);
        const float h0 = h0p[i];
        const float h1 = h1p[i];
        acc0.x = fmaf(h0, w4.x, acc0.x);
        acc0.y = fmaf(h0, w4.y, acc0.y);
        acc0.z = fmaf(h0, w4.z, acc0.z);
        acc0.w = fmaf(h0, w4.w, acc0.w);
        acc1.x = fmaf(h1, w4.x, acc1.x);
        acc1.y = fmaf(h1, w4.y, acc1.y);
        acc1.z = fmaf(h1, w4.z, acc1.z);
        acc1.w = fmaf(h1, w4.w, acc1.w);
    }

    const float d0 = g_dis[k0];
    const float d1 = g_dis[k0 + 1];
    __half2 p;
    p = __floats2half2_rn(acc0.x * d0, acc1.x * d1);
    *reinterpret_cast<__half2*>(&g_Bt[(size_t)(j0 + 0) * N_NODES + k0]) = p;
    p = __floats2half2_rn(acc0.y * d0, acc1.y * d1);
    *reinterpret_cast<__half2*>(&g_Bt[(size_t)(j0 + 1) * N_NODES + k0]) = p;
    p = __floats2half2_rn(acc0.z * d0, acc1.z * d1);
    *reinterpret_cast<__half2*>(&g_Bt[(size_t)(j0 + 2) * N_NODES + k0]) = p;
    p = __floats2half2_rn(acc0.w * d0, acc1.w * d1);
    *reinterpret_cast<__half2*>(&g_Bt[(size_t)(j0 + 3) * N_NODES + k0]) = p;
}

// ---------------------------------------------------------------------------
// K3: fp16 HMMA GEMM (R4 mainloop). A arrives as fp32 via cp.async into a
// linear staging buffer; a short in-smem pass converts it to the swizzled
// fp16 tile (double-buffered) consumed by ldmatrix. B fp16 as before.
// 128 CTAs (M=64), 256 thr.
// ---------------------------------------------------------------------------
__device__ __forceinline__ uint32_t s2u(const void* p) {
    uint32_t a;
    asm("{ .reg .u64 t; cvta.to.shared.u64 t, %1; cvt.u32.u64 %0, t; }"
        : "=r"(a) : "l"(p));
    return a;
}
__device__ __forceinline__ void cp16(uint32_t dst, const void* src) {
    asm volatile("cp.async.cg.shared.global [%0], [%1], 16;"
                 :: "r"(dst), "l"(src) : "memory");
}
__device__ __forceinline__ void ldsm4(uint32_t* r, uint32_t addr) {
    asm volatile("ldmatrix.sync.aligned.m8n8.x4.shared.b16 {%0,%1,%2,%3}, [%4];"
                 : "=r"(r[0]), "=r"(r[1]), "=r"(r[2]), "=r"(r[3]) : "r"(addr));
}
__device__ __forceinline__ void hmma(float* d, const uint32_t* a,
                                     uint32_t b0, uint32_t b1) {
    asm volatile(
        "mma.sync.aligned.m16n8k16.row.col.f32.f16.f16.f32 "
        "{%0,%1,%2,%3},{%4,%5,%6,%7},{%8,%9},{%0,%1,%2,%3};"
        : "+f"(d[0]), "+f"(d[1]), "+f"(d[2]), "+f"(d[3])
        : "r"(a[0]), "r"(a[1]), "r"(a[2]), "r"(a[3]), "r"(b0), "r"(b1));
}

__global__ void __launch_bounds__(256, 1) k_gemm_h(
    const float* __restrict__ Ap, float* __restrict__ out)
{
    extern __shared__ __align__(1024) char dsm[];   // 144 KB
    const int t   = threadIdx.x;
    const int wid = t >> 5, lane = t & 31;
    const int wm  = wid & 1;          // m slab (0..1) * 32
    const int wn  = wid >> 1;         // n slab (0..3) * 32
    const int m0  = blockIdx.x * BM;
    const uint32_t smBase = s2u(dsm);

    // ---- A32 staging map: thread t -> row t>>2, 4x16B at col (t&3)*64B
    const int ar  = t >> 2;                  // 0..63
    const int ac  = (t & 3) * 16;            // float col base (16 floats = 64B)
    const float* srcA = Ap + (size_t)(m0 + ar) * N_NODES + ac;
    const uint32_t dstA32 = ar * 256 + ac * 4;   // linear, 256B rows

    // ---- B staging map (R4): thread t -> row t>>3, 16B at col (t&7)*16
    const int sr  = t >> 3;                  // 0..31
    const __half* srcB = g_Bt + (size_t)sr * N_NODES + (t & 7) * 8;
    const uint32_t dstB = SWZ(sr * 128 + (t & 7) * 16);  // + 4096 per 32 rows

    // ---- convert map: thread t -> rows (t>>3) and (t>>3)+32, 8 fp32 each
    const uint32_t cvtSrc = (t >> 3) * 256 + (t & 7) * 32;   // in A32 tile
    const uint32_t cvtDst = SWZ((t >> 3) * 128 + (t & 7) * 16);

    // ---- ldmatrix address components (same as R4)
    const int lr16 = lane & 15;
    const int lhalf = (lane >> 4) * 16;
    uint32_t aBase[2], bBase[2];
    #pragma unroll
    for (int mt = 0; mt < 2; mt++)
        aBase[mt] = (wm * 32 + mt * 16 + lr16) * 128 + lhalf;
    #pragma unroll
    for (int bt = 0; bt < 2; bt++)
        bBase[bt] = (wn * 32 + bt * 16 + lr16) * 128 + lhalf;

    float acc[2][4][4];
    #pragma unroll
    for (int mt = 0; mt < 2; mt++)
        #pragma unroll
        for (int nt = 0; nt < 4; nt++)
            #pragma unroll
            for (int r = 0; r < 4; r++) acc[mt][nt][r] = 0.0f;

    // ---- prologue: issue STAGES-1 chunks (A32 + B)
    #pragma unroll
    for (int c = 0; c < STAGES - 1; c++) {
        const uint32_t sS = smBase + c * STAGE_B;
        const int ko = c * BKC;
        #pragma unroll
        for (int j = 0; j < 4; j++)
            cp16(sS + dstA32 + j * 16, srcA + ko + j * 4);
        #pragma unroll
        for (int rb = 0; rb < 4; rb++)
            cp16(sS + A32_TILE_B + dstB + rb * 4096,
                 srcB + ko + (size_t)rb * 32 * N_NODES);
        asm volatile("cp.async.commit_group;" ::: "memory");
    }

    for (int c = 0; c < NCHUNKS; c++) {
        asm volatile("cp.async.wait_group %0;" :: "n"(STAGES - 2) : "memory");
        __syncthreads();

        const uint32_t sOff = (c & (STAGES - 1)) * STAGE_B;
        const uint32_t a16 = smBase + A16_OFF + (c & 1) * A16_BUF_B;

        // ---- convert A32[stage] -> swizzled fp16 A16[c&1] (2 passes)
        #pragma unroll
        for (int p = 0; p < 2; p++) {
            const char* s = dsm + sOff + cvtSrc + p * 32 * 256;
            const float4 f0 = *reinterpret_cast<const float4*>(s);
            const float4 f1 = *reinterpret_cast<const float4*>(s + 16);
            __half2 h0 = __floats2half2_rn(f0.x, f0.y);
            __half2 h1 = __floats2half2_rn(f0.z, f0.w);
            __half2 h2 = __floats2half2_rn(f1.x, f1.y);
            __half2 h3 = __floats2half2_rn(f1.z, f1.w);
            uint4 u = make_uint4(*(uint32_t*)&h0, *(uint32_t*)&h1,
                                 *(uint32_t*)&h2, *(uint32_t*)&h3);
            *reinterpret_cast<uint4*>(
                dsm + A16_OFF + (c & 1) * A16_BUF_B + cvtDst + p * 32 * 128) = u;
        }
        __syncthreads();

        const uint32_t sB = smBase + sOff + A32_TILE_B;

        #pragma unroll
        for (int kk = 0; kk < BKC / 16; kk++) {
            uint32_t aF[2][4], bF[2][4];
            #pragma unroll
            for (int mt = 0; mt < 2; mt++)
                ldsm4(aF[mt], a16 + SWZ(aBase[mt] + kk * 32));
            #pragma unroll
            for (int bt = 0; bt < 2; bt++)
                ldsm4(bF[bt], sB + SWZ(bBase[bt] + kk * 32));
            #pragma unroll
            for (int mt = 0; mt < 2; mt++)
                #pragma unroll
                for (int nt = 0; nt < 4; nt++)
                    hmma(acc[mt][nt], aF[mt],
                         bF[nt >> 1][nt & 1], bF[nt >> 1][(nt & 1) + 2]);
        }

        // issue chunk c + STAGES-1
        const int cn = c + STAGES - 1;
        if (cn < NCHUNKS) {
            const uint32_t nS = smBase + (cn & (STAGES - 1)) * STAGE_B;
            const int ko = cn * BKC;
            #pragma unroll
            for (int j = 0; j < 4; j++)
                cp16(nS + dstA32 + j * 16, srcA + ko + j * 4);
            #pragma unroll
            for (int rb = 0; rb < 4; rb++)
                cp16(nS + A32_TILE_B + dstB + rb * 4096,
                     srcB + ko + (size_t)rb * 32 * N_NODES);
        }
        asm volatile("cp.async.commit_group;" ::: "memory");
    }

    // ---- epilogue: scale by dis[i], LeakyReLU, store
    const int gid = lane >> 2;
    const int cid = (lane & 3) * 2;
    #pragma unroll
    for (int mt = 0; mt < 2; mt++) {
        const int r0 = m0 + wm * 32 + mt * 16 + gid;
        const float d0 = g_dis[r0];
        const float d1 = g_dis[r0 + 8];
        #pragma unroll
        for (int nt = 0; nt < 4; nt++) {
            const int col = wn * 32 + nt * 8 + cid;
            float v0 = d0 * acc[mt][nt][0];
            float v1 = d0 * acc[mt][nt][1];
            float v2 = d1 * acc[mt][nt][2];
            float v3 = d1 * acc[mt][nt][3];
            v0 = (v0 >= 0.0f) ? v0 : NEG_SLOPE * v0;
            v1 = (v1 >= 0.0f) ? v1 : NEG_SLOPE * v1;
            v2 = (v2 >= 0.0f) ? v2 : NEG_SLOPE * v2;
            v3 = (v3 >= 0.0f) ? v3 : NEG_SLOPE * v3;
            *reinterpret_cast<float2*>(out + (size_t)r0 * D_OUT + col)
                = make_float2(v0, v1);
            *reinterpret_cast<float2*>(out + (size_t)(r0 + 8) * D_OUT + col)
                = make_float2(v2, v3);
        }
    }
}

// ---------------------------------------------------------------------------
extern "C" void kernel_launch(void* const* d_in, const int* in_sizes, int n_in,
                              void* d_out, int out_size)
{
    const float* H = (const float*)d_in[0];   // [8192, 200]
    const float* A = (const float*)d_in[1];   // [8192, 8192]
    const float* W = (const float*)d_in[2];   // [200, 128]
    const float* b = (const float*)d_in[3];   // [128]

    float* out  = (float*)d_out;                     // [8192, 128]
    float* Aout = out + (size_t)N_NODES * D_OUT;     // [8192, 8192] exact fp32 A'

    k_sigmoid_rowsum<<<N_NODES, 256>>>(A, Aout);
    k_hw<<<N_NODES / K2_ROWS, 256>>>(H, W, b);

    cudaFuncSetAttribute(k_gemm_h, cudaFuncAttributeMaxDynamicSharedMemorySize,
                         SMEM_TOT);
    k_gemm_h<<<N_NODES / BM, 256, SMEM_TOT>>>(Aout, out);
}

// round 11
// speedup vs baseline: 1.6847x; 1.0076x over previous
#include <cuda_runtime.h>
#include <cuda_fp16.h>
#include <cstdint>

// Shapes (fixed)
#define N_NODES 8192
#define D_IN    200
#define D_OUT   128
#define NEG_SLOPE 0.01f

// K3 tiling (R4 mainloop; A staged fp32, convert-ahead pipelined)
#define BM      64
#define BKC     64                     // K per chunk
#define NCHUNKS (N_NODES / BKC)        // 128
#define STAGES  4
#define A32_TILE_B (BM * BKC * 4)      // 16 KB fp32 A staging
#define B_TILE_B   (D_OUT * BKC * 2)   // 16 KB fp16 B
#define STAGE_B    (A32_TILE_B + B_TILE_B)        // 32 KB
#define A16_OFF    (STAGES * STAGE_B)             // 128 KB
#define A16_BUF_B  (BM * BKC * 2)                 // 8 KB
#define SMEM_TOT   (A16_OFF + 2 * A16_BUF_B)      // 144 KB
#define SWZ(off) ((off) ^ (((off) >> 3) & 0x70))

// Scratch (__device__ globals: allocation-free rule)
__device__ float  g_dis[N_NODES];                // d^{-1/2}
__device__ __half g_Bt[(size_t)D_OUT * N_NODES]; // [n][k] fp16 dis[k]*(HW+b)

// ---------------------------------------------------------------------------
// Kernel 1: A' = max(sigmoid(A), 0.1) -> fp32 output ONLY (512 MB); rowsums.
// (measured 77.8us at ~80% DRAM)
// ---------------------------------------------------------------------------
__global__ void __launch_bounds__(256) k_sigmoid_rowsum(
    const float* __restrict__ A, float* __restrict__ Aout)
{
    const int row = blockIdx.x;
    const float4* ap = reinterpret_cast<const float4*>(A + (size_t)row * N_NODES);
    float4* op = reinterpret_cast<float4*>(Aout + (size_t)row * N_NODES);

    float sum = 0.0f;
    #pragma unroll 2
    for (int i = threadIdx.x; i < N_NODES / 4; i += 256) {
        float4 v = ap[i];
        float4 s;
        s.x = fmaxf(__fdividef(1.0f, 1.0f + __expf(-v.x)), 0.1f);
        s.y = fmaxf(__fdividef(1.0f, 1.0f + __expf(-v.y)), 0.1f);
        s.z = fmaxf(__fdividef(1.0f, 1.0f + __expf(-v.z)), 0.1f);
        s.w = fmaxf(__fdividef(1.0f, 1.0f + __expf(-v.w)), 0.1f);
        op[i] = s;
        sum += (s.x + s.y) + (s.z + s.w);
    }

    #pragma unroll
    for (int off = 16; off > 0; off >>= 1)
        sum += __shfl_xor_sync(0xFFFFFFFFu, sum, off);

    __shared__ float ws[8];
    const int wid = threadIdx.x >> 5;
    const int lane = threadIdx.x & 31;
    if (lane == 0) ws[wid] = sum;
    __syncthreads();
    if (threadIdx.x == 0) {
        float tot = 0.0f;
        #pragma unroll
        for (int w = 0; w < 8; w++) tot += ws[w];
        g_dis[row] = rsqrtf(tot);
    }
}

// ---------------------------------------------------------------------------
// Kernel 2: g_Bt[j][k] = fp16( dis[k] * (H[k,:]@W[:,j] + b[j]) ) (transposed)
// ---------------------------------------------------------------------------
#define K2_ROWS 16
__global__ void __launch_bounds__(256) k_hw(
    const float* __restrict__ H, const float* __restrict__ W,
    const float* __restrict__ b)
{
    __shared__ float hs[K2_ROWS][D_IN];
    const int kb = blockIdx.x * K2_ROWS;
    const int tid = threadIdx.x;

    for (int idx = tid; idx < K2_ROWS * (D_IN / 4); idx += 256) {
        const int r = idx / (D_IN / 4), c = idx % (D_IN / 4);
        reinterpret_cast<float4*>(&hs[r][0])[c] =
            reinterpret_cast<const float4*>(H + (size_t)(kb + r) * D_IN)[c];
    }
    __syncthreads();

    const int ty = tid >> 5;
    const int tx = tid & 31;
    const int j0 = tx * 4;
    const int k0 = kb + ty * 2;

    const float4 bj = *reinterpret_cast<const float4*>(b + j0);
    float4 acc0 = bj, acc1 = bj;
    const float* h0p = hs[ty * 2];
    const float* h1p = hs[ty * 2 + 1];

    #pragma unroll 4
    for (int i = 0; i < D_IN; i++) {
        const float4 w4 = *reinterpret_cast<const float4*>(W + i * D_OUT + j0);
        const float h0 = h0p[i];
        const float h1 = h1p[i];
        acc0.x = fmaf(h0, w4.x, acc0.x);
        acc0.y = fmaf(h0, w4.y, acc0.y);
        acc0.z = fmaf(h0, w4.z, acc0.z);
        acc0.w = fmaf(h0, w4.w, acc0.w);
        acc1.x = fmaf(h1, w4.x, acc1.x);
        acc1.y = fmaf(h1, w4.y, acc1.y);
        acc1.z = fmaf(h1, w4.z, acc1.z);
        acc1.w = fmaf(h1, w4.w, acc1.w);
    }

    const float d0 = g_dis[k0];
    const float d1 = g_dis[k0 + 1];
    __half2 p;
    p = __floats2half2_rn(acc0.x * d0, acc1.x * d1);
    *reinterpret_cast<__half2*>(&g_Bt[(size_t)(j0 + 0) * N_NODES + k0]) = p;
    p = __floats2half2_rn(acc0.y * d0, acc1.y * d1);
    *reinterpret_cast<__half2*>(&g_Bt[(size_t)(j0 + 1) * N_NODES + k0]) = p;
    p = __floats2half2_rn(acc0.z * d0, acc1.z * d1);
    *reinterpret_cast<__half2*>(&g_Bt[(size_t)(j0 + 2) * N_NODES + k0]) = p;
    p = __floats2half2_rn(acc0.w * d0, acc1.w * d1);
    *reinterpret_cast<__half2*>(&g_Bt[(size_t)(j0 + 3) * N_NODES + k0]) = p;
}

// ---------------------------------------------------------------------------
// K3: fp16 HMMA GEMM. A arrives fp32 via cp.async; the fp32->fp16 swizzled
// convert of chunk c+1 runs CONCURRENTLY with the mma of chunk c (disjoint
// A16 double buffers; single barrier per chunk). 128 CTAs (M=64), 256 thr.
// ---------------------------------------------------------------------------
__device__ __forceinline__ uint32_t s2u(const void* p) {
    uint32_t a;
    asm("{ .reg .u64 t; cvta.to.shared.u64 t, %1; cvt.u32.u64 %0, t; }"
        : "=r"(a) : "l"(p));
    return a;
}
__device__ __forceinline__ void cp16(uint32_t dst, const void* src) {
    asm volatile("cp.async.cg.shared.global [%0], [%1], 16;"
                 :: "r"(dst), "l"(src) : "memory");
}
__device__ __forceinline__ void ldsm4(uint32_t* r, uint32_t addr) {
    asm volatile("ldmatrix.sync.aligned.m8n8.x4.shared.b16 {%0,%1,%2,%3}, [%4];"
                 : "=r"(r[0]), "=r"(r[1]), "=r"(r[2]), "=r"(r[3]) : "r"(addr));
}
__device__ __forceinline__ void hmma(float* d, const uint32_t* a,
                                     uint32_t b0, uint32_t b1) {
    asm volatile(
        "mma.sync.aligned.m16n8k16.row.col.f32.f16.f16.f32 "
        "{%0,%1,%2,%3},{%4,%5,%6,%7},{%8,%9},{%0,%1,%2,%3};"
        : "+f"(d[0]), "+f"(d[1]), "+f"(d[2]), "+f"(d[3])
        : "r"(a[0]), "r"(a[1]), "r"(a[2]), "r"(a[3]), "r"(b0), "r"(b1));
}

__global__ void __launch_bounds__(256, 1) k_gemm_h(
    const float* __restrict__ Ap, float* __restrict__ out)
{
    extern __shared__ __align__(1024) char dsm[];   // 144 KB
    const int t   = threadIdx.x;
    const int wid = t >> 5, lane = t & 31;
    const int wm  = wid & 1;          // m slab (0..1) * 32
    const int wn  = wid >> 1;         // n slab (0..3) * 32
    const int m0  = blockIdx.x * BM;
    const uint32_t smBase = s2u(dsm);

    // ---- A32 staging map: thread t -> row t>>2, 4x16B at col (t&3)*64B
    const int ar  = t >> 2;                  // 0..63
    const int ac  = (t & 3) * 16;            // float col base
    const float* srcA = Ap + (size_t)(m0 + ar) * N_NODES + ac;
    const uint32_t dstA32 = ar * 256 + ac * 4;   // linear, 256B rows

    // ---- B staging map: thread t -> row t>>3, 16B at col (t&7)*16
    const int sr  = t >> 3;                  // 0..31
    const __half* srcB = g_Bt + (size_t)sr * N_NODES + (t & 7) * 8;
    const uint32_t dstB = SWZ(sr * 128 + (t & 7) * 16);  // + 4096 per 32 rows

    // ---- convert map: thread t -> rows (t>>3), (t>>3)+32; 8 fp32 each
    const uint32_t cvtSrc = (t >> 3) * 256 + (t & 7) * 32;   // in A32 tile
    const uint32_t cvtDst = SWZ((t >> 3) * 128 + (t & 7) * 16);

    // ---- ldmatrix address components
    const int lr16 = lane & 15;
    const int lhalf = (lane >> 4) * 16;
    uint32_t aBase[2], bBase[2];
    #pragma unroll
    for (int mt = 0; mt < 2; mt++)
        aBase[mt] = (wm * 32 + mt * 16 + lr16) * 128 + lhalf;
    #pragma unroll
    for (int bt = 0; bt < 2; bt++)
        bBase[bt] = (wn * 32 + bt * 16 + lr16) * 128 + lhalf;

    float acc[2][4][4];
    #pragma unroll
    for (int mt = 0; mt < 2; mt++)
        #pragma unroll
        for (int nt = 0; nt < 4; nt++)
            #pragma unroll
            for (int r = 0; r < 4; r++) acc[mt][nt][r] = 0.0f;

    // convert helper (chunk ck -> A16[ck&1]); caller guarantees A32 resident
    auto convert_chunk = [&](int ck) {
        const uint32_t sOff = (ck & (STAGES - 1)) * STAGE_B;
        const uint32_t dOff = A16_OFF + (ck & 1) * A16_BUF_B;
        #pragma unroll
        for (int p = 0; p < 2; p++) {
            const char* s = dsm + sOff + cvtSrc + p * 32 * 256;
            const float4 f0 = *reinterpret_cast<const float4*>(s);
            const float4 f1 = *reinterpret_cast<const float4*>(s + 16);
            __half2 h0 = __floats2half2_rn(f0.x, f0.y);
            __half2 h1 = __floats2half2_rn(f0.z, f0.w);
            __half2 h2 = __floats2half2_rn(f1.x, f1.y);
            __half2 h3 = __floats2half2_rn(f1.z, f1.w);
            uint4 u = make_uint4(*(uint32_t*)&h0, *(uint32_t*)&h1,
                                 *(uint32_t*)&h2, *(uint32_t*)&h3);
            *reinterpret_cast<uint4*>(dsm + dOff + cvtDst + p * 32 * 128) = u;
        }
    };

    // ---- prologue: issue chunks 0..2 (A32 + B)
    #pragma unroll
    for (int c = 0; c < STAGES - 1; c++) {
        const uint32_t sS = smBase + c * STAGE_B;
        const int ko = c * BKC;
        #pragma unroll
        for (int j = 0; j < 4; j++)
            cp16(sS + dstA32 + j * 16, srcA + ko + j * 4);
        #pragma unroll
        for (int rb = 0; rb < 4; rb++)
            cp16(sS + A32_TILE_B + dstB + rb * 4096,
                 srcB + ko + (size_t)rb * 32 * N_NODES);
        asm volatile("cp.async.commit_group;" ::: "memory");
    }
    // convert chunk 0 ahead of the loop
    asm volatile("cp.async.wait_group %0;" :: "n"(2) : "memory");
    __syncthreads();
    convert_chunk(0);

    for (int c = 0; c < NCHUNKS; c++) {
        // chunks <= c+1 complete (newest committed = c+2 stays pending)
        asm volatile("cp.async.wait_group %0;" :: "n"(1) : "memory");
        __syncthreads();   // publishes prev iter's convert + guards stage reuse

        // convert chunk c+1 (A16[(c+1)&1]) — overlaps with the mma below
        if (c + 1 < NCHUNKS) convert_chunk(c + 1);

        const uint32_t a16 = smBase + A16_OFF + (c & 1) * A16_BUF_B;
        const uint32_t sB  = smBase + (c & (STAGES - 1)) * STAGE_B + A32_TILE_B;

        #pragma unroll
        for (int kk = 0; kk < BKC / 16; kk++) {
            uint32_t aF[2][4], bF[2][4];
            #pragma unroll
            for (int mt = 0; mt < 2; mt++)
                ldsm4(aF[mt], a16 + SWZ(aBase[mt] + kk * 32));
            #pragma unroll
            for (int bt = 0; bt < 2; bt++)
                ldsm4(bF[bt], sB + SWZ(bBase[bt] + kk * 32));
            #pragma unroll
            for (int mt = 0; mt < 2; mt++)
                #pragma unroll
                for (int nt = 0; nt < 4; nt++)
                    hmma(acc[mt][nt], aF[mt],
                         bF[nt >> 1][nt & 1], bF[nt >> 1][(nt & 1) + 2]);
        }

        // issue chunk c + 3
        const int cn = c + STAGES - 1;
        if (cn < NCHUNKS) {
            const uint32_t nS = smBase + (cn & (STAGES - 1)) * STAGE_B;
            const int ko = cn * BKC;
            #pragma unroll
            for (int j = 0; j < 4; j++)
                cp16(nS + dstA32 + j * 16, srcA + ko + j * 4);
            #pragma unroll
            for (int rb = 0; rb < 4; rb++)
                cp16(nS + A32_TILE_B + dstB + rb * 4096,
                     srcB + ko + (size_t)rb * 32 * N_NODES);
        }
        asm volatile("cp.async.commit_group;" ::: "memory");
    }

    // ---- epilogue: scale by dis[i], LeakyReLU, store
    const int gid = lane >> 2;
    const int cid = (lane & 3) * 2;
    #pragma unroll
    for (int mt = 0; mt < 2; mt++) {
        const int r0 = m0 + wm * 32 + mt * 16 + gid;
        const float d0 = g_dis[r0];
        const float d1 = g_dis[r0 + 8];
        #pragma unroll
        for (int nt = 0; nt < 4; nt++) {
            const int col = wn * 32 + nt * 8 + cid;
            float v0 = d0 * acc[mt][nt][0];
            float v1 = d0 * acc[mt][nt][1];
            float v2 = d1 * acc[mt][nt][2];
            float v3 = d1 * acc[mt][nt][3];
            v0 = (v0 >= 0.0f) ? v0 : NEG_SLOPE * v0;
            v1 = (v1 >= 0.0f) ? v1 : NEG_SLOPE * v1;
            v2 = (v2 >= 0.0f) ? v2 : NEG_SLOPE * v2;
            v3 = (v3 >= 0.0f) ? v3 : NEG_SLOPE * v3;
            *reinterpret_cast<float2*>(out + (size_t)r0 * D_OUT + col)
                = make_float2(v0, v1);
            *reinterpret_cast<float2*>(out + (size_t)(r0 + 8) * D_OUT + col)
                = make_float2(v2, v3);
        }
    }
}

// ---------------------------------------------------------------------------
extern "C" void kernel_launch(void* const* d_in, const int* in_sizes, int n_in,
                              void* d_out, int out_size)
{
    const float* H = (const float*)d_in[0];   // [8192, 200]
    const float* A = (const float*)d_in[1];   // [8192, 8192]
    const float* W = (const float*)d_in[2];   // [200, 128]
    const float* b = (const float*)d_in[3];   // [128]

    float* out  = (float*)d_out;                     // [8192, 128]
    float* Aout = out + (size_t)N_NODES * D_OUT;     // [8192, 8192] exact fp32 A'

    k_sigmoid_rowsum<<<N_NODES, 256>>>(A, Aout);
    k_hw<<<N_NODES / K2_ROWS, 256>>>(H, W, b);

    cudaFuncSetAttribute(k_gemm_h, cudaFuncAttributeMaxDynamicSharedMemorySize,
                         SMEM_TOT);
    k_gemm_h<<<N_NODES / BM, 256, SMEM_TOT>>>(Aout, out);
}